// round 2
// baseline (speedup 1.0000x reference)
#include <cuda_runtime.h>
#include <math.h>

#define D 128
#define NMAX 100000

// Scratch (static __device__ — no allocations allowed)
__device__ float  g_h [(size_t)NMAX * D];
__device__ float  g_y1[(size_t)NMAX * D];
__device__ float  g_y2[(size_t)NMAX * D];
__device__ double g_acc[6];   // (sum, sumsq) x 3 layernorms
__device__ float  g_ms[6];    // (mean, inv_std) x 3

// ---------------------------------------------------------------------------
// K0: h = (1+eps)*node ; zero the stats accumulators
// ---------------------------------------------------------------------------
__global__ void k_init(const float* __restrict__ node, const float* __restrict__ epsp, int n) {
    if (blockIdx.x == 0 && threadIdx.x < 6) g_acc[threadIdx.x] = 0.0;
    int i = blockIdx.x * blockDim.x + threadIdx.x;
    int total = n * (D / 4);
    if (i < total) {
        float s = 1.0f + __ldg(epsp);
        float4 v = __ldg(((const float4*)node) + i);
        v.x *= s; v.y *= s; v.z *= s; v.w *= s;
        ((float4*)g_h)[i] = v;
    }
}

// ---------------------------------------------------------------------------
// K1: scatter-add node[src] row into g_h[dst] row. One warp per edge.
// Vectorized reduction (red.global.add.v4.f32, sm_90+) -> 4x fewer L2 atomics.
// ---------------------------------------------------------------------------
__global__ void k_scatter(const int* __restrict__ ei, const float* __restrict__ node, int ne) {
    int gw   = (blockIdx.x * blockDim.x + threadIdx.x) >> 5;
    int lane = threadIdx.x & 31;
    if (gw >= ne) return;
    int src = __ldg(ei + gw);
    int dst = __ldg(ei + ne + gw);
    float4 v = __ldg((const float4*)(node + (size_t)src * D) + lane);
    float* addr = g_h + (size_t)dst * D + lane * 4;
    asm volatile("red.global.add.v4.f32 [%0], {%1,%2,%3,%4};"
                 :: "l"(addr), "f"(v.x), "f"(v.y), "f"(v.z), "f"(v.w) : "memory");
}

// ---------------------------------------------------------------------------
// GEMM: Y[n,128] = transform(A)[n,128] @ W[128,128] + bias
//  - optional fused input transform: relu((a-mean)*inv * ln_w[k] + ln_b[k])
//  - fused epilogue stats: sum & sumsq of Y -> double atomics (for next LN)
//  - f32x2 packed FFMA2 inner loop (2 FMA / instr / lane)
// Block: 256 thr, tile 64 rows x 128 cols, thread tile 4x8 (4 f32x2 col-pairs)
// ---------------------------------------------------------------------------
__device__ __forceinline__ unsigned long long dupf(float x) {
    unsigned long long r;
    unsigned u = __float_as_uint(x);
    asm("mov.b64 %0, {%1,%1};" : "=l"(r) : "r"(u));
    return r;
}
#define FMA2(acc, a, b) asm("fma.rn.f32x2 %0, %1, %2, %0;" : "+l"(acc) : "l"(a), "l"(b))

template<bool LN>
__global__ void k_gemm(const float* __restrict__ A, const float* __restrict__ W,
                       const float* __restrict__ bias,
                       const float* __restrict__ lnw, const float* __restrict__ lnb,
                       const float* __restrict__ ms,
                       float* __restrict__ Y, double* __restrict__ acc_out, int n)
{
    extern __shared__ __align__(16) char smem[];
    float* Ws  = (float*)smem;                    // 128*128 floats = 64KB
    float* As  = (float*)(smem + 65536);          // 16*64 floats   = 4KB
    float* red = (float*)(smem + 65536 + 4096);   // 16 floats

    int tid = threadIdx.x;
    int tx = tid & 15, ty = tid >> 4;             // 16 col-groups x 16 row-groups
    int row0 = blockIdx.x * 64;

    // Stage full W into smem
    {
        const float4* W4 = (const float4*)W;
        float4* Ws4 = (float4*)Ws;
        #pragma unroll
        for (int i = 0; i < 16; i++) Ws4[tid + 256 * i] = __ldg(W4 + tid + 256 * i);
    }

    float mean = 0.f, inv = 0.f;
    if constexpr (LN) { mean = __ldg(ms); inv = __ldg(ms + 1); }

    int r  = tid >> 2;             // 0..63 : row this thread loads
    int kg = (tid & 3) * 4;        // k-subgroup within 16-wide chunk
    int grow_ld = row0 + r;

    auto loadA = [&](int c) -> float4 {
        float4 v = make_float4(0.f, 0.f, 0.f, 0.f);
        if (grow_ld < n) {
            v = __ldg((const float4*)(A + (size_t)grow_ld * D + c * 16 + kg));
            if constexpr (LN) {
                int kb = c * 16 + kg;
                float4 wv = __ldg((const float4*)(lnw + kb));
                float4 bv = __ldg((const float4*)(lnb + kb));
                v.x = fmaxf(fmaf((v.x - mean) * inv, wv.x, bv.x), 0.f);
                v.y = fmaxf(fmaf((v.y - mean) * inv, wv.y, bv.y), 0.f);
                v.z = fmaxf(fmaf((v.z - mean) * inv, wv.z, bv.z), 0.f);
                v.w = fmaxf(fmaf((v.w - mean) * inv, wv.w, bv.w), 0.f);
            }
        }
        return v;
    };

    float4 areg = loadA(0);

    unsigned long long acc[4][4];
    #pragma unroll
    for (int j = 0; j < 4; j++)
        #pragma unroll
        for (int p = 0; p < 4; p++) acc[j][p] = 0ULL;

    for (int c = 0; c < 8; c++) {
        __syncthreads();                       // previous chunk fully consumed
        As[(kg + 0) * 64 + r] = areg.x;
        As[(kg + 1) * 64 + r] = areg.y;
        As[(kg + 2) * 64 + r] = areg.z;
        As[(kg + 3) * 64 + r] = areg.w;
        __syncthreads();
        if (c < 7) areg = loadA(c + 1);        // prefetch next chunk behind compute

        #pragma unroll
        for (int kk = 0; kk < 16; kk++) {
            int k = c * 16 + kk;
            float4 av = *(const float4*)&As[kk * 64 + ty * 4];
            ulonglong2 b0 = *(const ulonglong2*)&Ws[k * 128 + tx * 8];
            ulonglong2 b1 = *(const ulonglong2*)&Ws[k * 128 + tx * 8 + 4];
            unsigned long long a0 = dupf(av.x), a1 = dupf(av.y);
            unsigned long long a2 = dupf(av.z), a3 = dupf(av.w);
            FMA2(acc[0][0], a0, b0.x); FMA2(acc[0][1], a0, b0.y);
            FMA2(acc[0][2], a0, b1.x); FMA2(acc[0][3], a0, b1.y);
            FMA2(acc[1][0], a1, b0.x); FMA2(acc[1][1], a1, b0.y);
            FMA2(acc[1][2], a1, b1.x); FMA2(acc[1][3], a1, b1.y);
            FMA2(acc[2][0], a2, b0.x); FMA2(acc[2][1], a2, b0.y);
            FMA2(acc[2][2], a2, b1.x); FMA2(acc[2][3], a2, b1.y);
            FMA2(acc[3][0], a3, b0.x); FMA2(acc[3][1], a3, b0.y);
            FMA2(acc[3][2], a3, b1.x); FMA2(acc[3][3], a3, b1.y);
        }
    }

    // Epilogue: unpack, add bias, store, accumulate LN stats
    float4 bo0 = __ldg((const float4*)(bias + tx * 8));
    float4 bo1 = __ldg((const float4*)(bias + tx * 8 + 4));
    float lsum = 0.f, lsq = 0.f;
    #pragma unroll
    for (int j = 0; j < 4; j++) {
        int grow = row0 + ty * 4 + j;
        if (grow < n) {
            float o[8];
            #pragma unroll
            for (int p = 0; p < 4; p++) {
                unsigned lo, hi;
                asm("mov.b64 {%0,%1}, %2;" : "=r"(lo), "=r"(hi) : "l"(acc[j][p]));
                o[2 * p]     = __uint_as_float(lo);
                o[2 * p + 1] = __uint_as_float(hi);
            }
            o[0] += bo0.x; o[1] += bo0.y; o[2] += bo0.z; o[3] += bo0.w;
            o[4] += bo1.x; o[5] += bo1.y; o[6] += bo1.z; o[7] += bo1.w;
            float4* yp = (float4*)(Y + (size_t)grow * D + tx * 8);
            yp[0] = make_float4(o[0], o[1], o[2], o[3]);
            yp[1] = make_float4(o[4], o[5], o[6], o[7]);
            #pragma unroll
            for (int q = 0; q < 8; q++) { lsum += o[q]; lsq += o[q] * o[q]; }
        }
    }
    #pragma unroll
    for (int off = 16; off; off >>= 1) {
        lsum += __shfl_xor_sync(0xffffffffu, lsum, off);
        lsq  += __shfl_xor_sync(0xffffffffu, lsq,  off);
    }
    int wid = tid >> 5, lane = tid & 31;
    if (lane == 0) { red[wid] = lsum; red[8 + wid] = lsq; }
    __syncthreads();
    if (tid == 0) {
        float s = 0.f, q = 0.f;
        #pragma unroll
        for (int w = 0; w < 8; w++) { s += red[w]; q += red[8 + w]; }
        atomicAdd(acc_out,     (double)s);
        atomicAdd(acc_out + 1, (double)q);
    }
}

// ---------------------------------------------------------------------------
// Stats finalize: mean, 1/(std + 1e-5)
// ---------------------------------------------------------------------------
__global__ void k_fin(const double* __restrict__ acc, float* __restrict__ ms, double cnt) {
    double m = acc[0] / cnt;
    double var = acc[1] / cnt - m * m;
    if (var < 0.0) var = 0.0;
    ms[0] = (float)m;
    ms[1] = 1.0f / ((float)sqrt(var) + 1e-5f);
}

// ---------------------------------------------------------------------------
// Final: out = relu(LN(out)) in place
// ---------------------------------------------------------------------------
__global__ void k_final(float* __restrict__ y, const float* __restrict__ lnw,
                        const float* __restrict__ lnb, const float* __restrict__ ms, int n) {
    int i = blockIdx.x * blockDim.x + threadIdx.x;
    if (i >= n * (D / 4)) return;
    float mean = __ldg(ms), inv = __ldg(ms + 1);
    float4 v = ((float4*)y)[i];
    int kb = (i * 4) & (D - 1);
    float4 wv = __ldg((const float4*)(lnw + kb));
    float4 bv = __ldg((const float4*)(lnb + kb));
    v.x = fmaxf(fmaf((v.x - mean) * inv, wv.x, bv.x), 0.f);
    v.y = fmaxf(fmaf((v.y - mean) * inv, wv.y, bv.y), 0.f);
    v.z = fmaxf(fmaf((v.z - mean) * inv, wv.z, bv.z), 0.f);
    v.w = fmaxf(fmaf((v.w - mean) * inv, wv.w, bv.w), 0.f);
    ((float4*)y)[i] = v;
}

// ---------------------------------------------------------------------------
extern "C" void kernel_launch(void* const* d_in, const int* in_sizes, int n_in,
                              void* d_out, int out_size) {
    const float* node = (const float*)d_in[0];
    const int*   ei   = (const int*)d_in[1];
    const float* epsp = (const float*)d_in[4];
    const float* W1 = (const float*)d_in[5];  const float* b1 = (const float*)d_in[6];
    const float* l1w = (const float*)d_in[7]; const float* l1b = (const float*)d_in[8];
    const float* W2 = (const float*)d_in[9];  const float* b2 = (const float*)d_in[10];
    const float* l2w = (const float*)d_in[11]; const float* l2b = (const float*)d_in[12];
    const float* W3 = (const float*)d_in[13]; const float* b3 = (const float*)d_in[14];
    const float* low = (const float*)d_in[15]; const float* lob = (const float*)d_in[16];
    float* out = (float*)d_out;

    int n  = in_sizes[0] / D;
    int ne = in_sizes[1] / 2;

    float *hP, *y1P, *y2P, *msP; double* accP;
    cudaGetSymbolAddress((void**)&hP,  g_h);
    cudaGetSymbolAddress((void**)&y1P, g_y1);
    cudaGetSymbolAddress((void**)&y2P, g_y2);
    cudaGetSymbolAddress((void**)&accP, g_acc);
    cudaGetSymbolAddress((void**)&msP,  g_ms);

    const int smem = 65536 + 4096 + 64;
    cudaFuncSetAttribute(k_gemm<false>, cudaFuncAttributeMaxDynamicSharedMemorySize, smem);
    cudaFuncSetAttribute(k_gemm<true>,  cudaFuncAttributeMaxDynamicSharedMemorySize, smem);

    int t4 = n * (D / 4);
    double cnt = (double)n * D;
    int gb = (n + 63) / 64;

    k_init<<<(t4 + 255) / 256, 256>>>(node, epsp, n);
    k_scatter<<<(ne + 7) / 8, 256>>>(ei, node, ne);
    k_gemm<false><<<gb, 256, smem>>>(hP,  W1, b1, nullptr, nullptr, nullptr, y1P, accP,     n);
    k_fin<<<1, 1>>>(accP,     msP,     cnt);
    k_gemm<true><<<gb, 256, smem>>>(y1P, W2, b2, l1w, l1b, msP,     y2P, accP + 2, n);
    k_fin<<<1, 1>>>(accP + 2, msP + 2, cnt);
    k_gemm<true><<<gb, 256, smem>>>(y2P, W3, b3, l2w, l2b, msP + 2, out, accP + 4, n);
    k_fin<<<1, 1>>>(accP + 4, msP + 4, cnt);
    k_final<<<(t4 + 255) / 256, 256>>>(out, low, lob, msP + 4, n);
}